// round 10
// baseline (speedup 1.0000x reference)
#include <cuda_runtime.h>
#include <cuda_fp16.h>
#include <cstdint>
#include <cstddef>

#define NB 128
#define NS 512
#define ND 128
#define NH 1024
#define NO 64
#define NIN 257
#define KP 264
#define NG 4096

// ---------------- device scratch ----------------
__device__ __align__(16) float d_xt[NS * NB * KP];
__device__ __align__(16) float d_wih[NG * KP];
__device__ __align__(16) __half d_whh16[NG * NH];
__device__ __align__(16) float d_bias[NG];
__device__ __align__(16) float d_xg[(size_t)NS * NB * NG];
__device__ __align__(1024) __half d_h16[2][NB * NH];   // permuted+swizzled layout
__device__ __align__(16) int d_pflag[128 * 8];         // producer step flags (stride 8)

// ---------------- helpers ----------------
__device__ __forceinline__ unsigned smem_u32(const void* p) {
    return (unsigned)__cvta_generic_to_shared(p);
}
__device__ __forceinline__ void cpa16(unsigned s, const void* g) {
    asm volatile("cp.async.cg.shared.global [%0], [%1], 16;\n" :: "r"(s), "l"(g));
}
__device__ __forceinline__ void cp_commit() { asm volatile("cp.async.commit_group;\n"); }
__device__ __forceinline__ void cp_wait0() { asm volatile("cp.async.wait_group 0;\n" ::: "memory"); }
__device__ __forceinline__ void cp_wait1() { asm volatile("cp.async.wait_group 1;\n" ::: "memory"); }
__device__ __forceinline__ void cp_wait12() { asm volatile("cp.async.wait_group 12;\n" ::: "memory"); }

__device__ __forceinline__ float to_tf32(float x) {
    asm("cvt.rna.tf32.f32 %0, %0;" : "+f"(x));
    return x;
}
__device__ __forceinline__ float sigf(float x) { return 1.f / (1.f + __expf(-x)); }
__device__ __forceinline__ float tanhf_(float x) {
    float e = __expf(-2.f * fabsf(x));
    float t = (1.f - e) / (1.f + e);
    return copysignf(t, x);
}

// fp16 HMMA m16n8k16, fp32 accum
__device__ __forceinline__ void mma16(float* c, const unsigned* a, const unsigned* b) {
    asm volatile(
        "mma.sync.aligned.m16n8k16.row.col.f32.f16.f16.f32 "
        "{%0,%1,%2,%3}, {%4,%5,%6,%7}, {%8,%9}, {%0,%1,%2,%3};\n"
        : "+f"(c[0]), "+f"(c[1]), "+f"(c[2]), "+f"(c[3])
        : "r"(a[0]), "r"(a[1]), "r"(a[2]), "r"(a[3]), "r"(b[0]), "r"(b[1]));
}
// tf32 HMMA for k_xg
__device__ __forceinline__ void mma8(float* c, const unsigned* a, const unsigned* b) {
    asm volatile(
        "mma.sync.aligned.m16n8k8.row.col.f32.tf32.tf32.f32 "
        "{%0,%1,%2,%3}, {%4,%5,%6,%7}, {%8,%9}, {%0,%1,%2,%3};\n"
        : "+f"(c[0]), "+f"(c[1]), "+f"(c[2]), "+f"(c[3])
        : "r"(a[0]), "r"(a[1]), "r"(a[2]), "r"(a[3]), "r"(b[0]), "r"(b[1]));
}

// ---------------- prep kernels ----------------
__global__ void k_prep_xt(const float* __restrict__ x, const float* __restrict__ mask,
                          const float* __restrict__ ti) {
    int idx = blockIdx.x * 256 + threadIdx.x;
    if (idx >= NS * NB * KP) return;
    int r = idx / KP, k = idx - r * KP;
    int s = r >> 7, b = r & 127;
    float v = 0.f;
    if (k < ND)            v = x[(b * NS + s) * ND + k];
    else if (k < 2 * ND)   v = mask[(b * NS + s) * ND + (k - ND)];
    else if (k == 2 * ND)  v = ti[b * NS + s];
    d_xt[idx] = to_tf32(v);
}

__global__ void k_prep_w(const float* __restrict__ wih, const float* __restrict__ whh,
                         const float* __restrict__ bih, const float* __restrict__ bhh) {
    int idx = blockIdx.x * 256 + threadIdx.x;
    if (idx < NG * KP) {
        int g = idx / KP, k = idx - g * KP;
        float v = (k < NIN) ? wih[g * NIN + k] : 0.f;
        d_wih[idx] = to_tf32(v);
    }
    if (idx < NG * NH) d_whh16[idx] = __float2half_rn(whh[idx]);
    if (idx < NG) d_bias[idx] = bih[idx] + bhh[idx];
    if (idx < 1024) d_pflag[idx] = 0;                          // reset flags each launch
    if (idx < 16384) ((uint4*)&d_h16[0][0])[idx] = make_uint4(0, 0, 0, 0);  // h0 = 0
}

// ---------------- XG GEMM (tf32 HMMA, unchanged) ----------------
#define XA_STRIDE 28
#define XW_STRIDE 268
#define XG_SMEM (64 * XW_STRIDE * 4 + 2 * 128 * XA_STRIDE * 4)

__global__ void __launch_bounds__(256, 2) k_xg() {
    extern __shared__ float sm[];
    float* Wsm = sm;
    float* Asm = sm + 64 * XW_STRIDE;
    const int tid = threadIdx.x;
    const int bx = blockIdx.x;
    const int s = blockIdx.y;
    const int n0 = bx * 64;
    const int row0 = s * NB;

    unsigned wbase = smem_u32(Wsm);
    unsigned abase = smem_u32(Asm);

    for (int q = tid; q < 64 * 66; q += 256) {
        int r = q / 66, c = q - r * 66;
        cpa16(wbase + (unsigned)(r * XW_STRIDE + c * 4) * 4, d_wih + (n0 + r) * KP + c * 4);
    }
    for (int q = tid; q < 128 * 6; q += 256) {
        int r = q / 6, c = q - r * 6;
        cpa16(abase + (unsigned)(r * XA_STRIDE + c * 4) * 4, d_xt + (row0 + r) * KP + c * 4);
    }
    cp_commit();

    const int wid = tid >> 5, l = tid & 31;
    const int wm = wid >> 1, wn = wid & 1;
    const int lr = l >> 2, lc = l & 3;

    float acc[2][4][4];
#pragma unroll
    for (int i = 0; i < 2; i++)
#pragma unroll
        for (int j = 0; j < 4; j++)
#pragma unroll
            for (int k = 0; k < 4; k++) acc[i][j][k] = 0.f;

    for (int st = 0; st < 11; st++) {
        float* Ab = Asm + (st & 1) * 128 * XA_STRIDE;
        if (st < 10) {
            unsigned anb = abase + (unsigned)(((st + 1) & 1) * 128 * XA_STRIDE) * 4;
            int kb = (st + 1) * 24;
            for (int q = tid; q < 128 * 6; q += 256) {
                int r = q / 6, c = q - r * 6;
                cpa16(anb + (unsigned)(r * XA_STRIDE + c * 4) * 4,
                      d_xt + (row0 + r) * KP + kb + c * 4);
            }
            cp_commit();
            cp_wait1();
        } else {
            cp_wait0();
        }
        __syncthreads();
#pragma unroll
        for (int k8 = 0; k8 < 3; k8++) {
            int kk = k8 * 8;
            unsigned afr[2][4];
#pragma unroll
            for (int mt = 0; mt < 2; mt++) {
                const float* p = Ab + (wm * 32 + mt * 16 + lr) * XA_STRIDE + kk + lc;
                afr[mt][0] = __float_as_uint(p[0]);
                afr[mt][1] = __float_as_uint(p[8 * XA_STRIDE]);
                afr[mt][2] = __float_as_uint(p[4]);
                afr[mt][3] = __float_as_uint(p[8 * XA_STRIDE + 4]);
            }
#pragma unroll
            for (int nt = 0; nt < 4; nt++) {
                const float* p = Wsm + (wn * 32 + nt * 8 + lr) * XW_STRIDE + st * 24 + kk + lc;
                unsigned bfr[2] = { __float_as_uint(p[0]), __float_as_uint(p[4]) };
#pragma unroll
                for (int mt = 0; mt < 2; mt++) mma8(acc[mt][nt], afr[mt], bfr);
            }
        }
        __syncthreads();
    }

#pragma unroll
    for (int mt = 0; mt < 2; mt++) {
#pragma unroll
        for (int nt = 0; nt < 4; nt++) {
            int g = n0 + wn * 32 + nt * 8 + 2 * lc;
            float2 bias = *(const float2*)(d_bias + g);
#pragma unroll
            for (int p = 0; p < 2; p++) {
                int row = row0 + wm * 32 + mt * 16 + lr + p * 8;
                float2 o;
                o.x = acc[mt][nt][2 * p + 0] + bias.x;
                o.y = acc[mt][nt][2 * p + 1] + bias.y;
                *(float2*)(d_xg + (size_t)row * NG + g) = o;
            }
        }
    }
}

// ---------------- persistent recurrent kernel ----------------
// 128 CTAs (1/SM). CTA cid owns hidden units [8*cid, 8*cid+8) = 32 gate cols (N=32).
// 8 warps = 2 k-halves (kh) x 4 m-quarters (mh, 32 rows). Warp: M=32, N=32, K=512
// as 32 iters of k16, 1 KB A per iter, 14-slot ring, prefetch distance 12 (empty
// commit groups keep the wait a fixed wait_group 12).
// Warp kh polls its 64 producer CTAs' flags (2 per lane); union over kh warps +
// the reduce syncthreads covers all 128 producers, preserving the R9 WAR argument.
// Reduction: kh0 warps -> R0, kh1 -> R1 (disjoint stores), ONE sync, epilogue sums.
#define R_PF     12
#define R_SLOTS  14
#define R_RSTRIDE 40
#define R_W_OFF   0                      /* 65536 B: W slice */
#define R_A_OFF   65536                  /* 114688 B: 8 warps x 14 slots x 1024 B */
#define R_R0_OFF  180224                 /* 20480 B */
#define R_R1_OFF  200704                 /* 20480 B */
#define R_SMEM    221184

__global__ void __launch_bounds__(256, 1) k_rec() {
    extern __shared__ char smraw[];
    __half* Wsm = (__half*)(smraw + R_W_OFF);
    __half* Aring = (__half*)(smraw + R_A_OFF);
    float* R0 = (float*)(smraw + R_R0_OFF);
    float* R1 = (float*)(smraw + R_R1_OFF);

    const int tid = threadIdx.x;
    const int w = tid >> 5, lane = tid & 31;
    const int kh = w & 1, mh = w >> 1;
    const int cid = blockIdx.x;
    const int J0 = cid * 8;
    const int lr = lane >> 2, lc = lane & 3;

    __half* Aw = Aring + w * (R_SLOTS * 512);
    const unsigned awbase = smem_u32(Aw);

    // ---- W slice -> Wsm (permuted + swizzled) ----
    for (int q = tid; q < 32768; q += 256) {
        int n = q >> 10, k = q & 1023;
        int g = n >> 3, u = n & 7;
        __half v = d_whh16[(size_t)(g * 1024 + J0 + u) * NH + k];
        int tb = k >> 4, j = (k >> 1) & 7;
        int p = j & 3, hs = j >> 2;
        int slot = p ^ (n & 3);
        Wsm[tb * 512 + n * 16 + slot * 4 + hs * 2 + (k & 1)] = v;
    }
    __syncthreads();

    // persistent cell state: thread owns items idx = tid + 256q -> (m = idx>>2, u = idx&3)
    float creg[2][2] = {{0.f, 0.f}, {0.f, 0.f}};

    // cp.async chunk map: 64 chunks of 16B per iter tile (32 rows x 32B);
    // lane handles chunks lane and lane+32 -> rows lane>>1 and 16+(lane>>1)
    const int f_r0 = lane >> 1, f_r1 = 16 + (lane >> 1);
    const int f_c = lane & 1;
    const int* flag0 = d_pflag + (64 * kh + lane) * 8;
    const int* flag1 = d_pflag + (64 * kh + 32 + lane) * 8;

    for (int s = 0; s < NS; s++) {
        const __half* hr = &d_h16[s & 1][0];
        __half* hw = &d_h16[(s + 1) & 1][0];
        const float* xgS = d_xg + (size_t)s * NB * NG;

        // prefetch xg (consumed in epilogue) — issued before the poll to overlap
        float2 xgr[2][4];
#pragma unroll
        for (int q = 0; q < 2; q++) {
            int idx = tid + q * 256;
            int m = idx >> 2, u = idx & 3;
            const float* xp = xgS + (size_t)m * NG + J0 + 2 * u;
#pragma unroll
            for (int g = 0; g < 4; g++)
                xgr[q][g] = __ldg((const float2*)(xp + g * 1024));
        }

        // ---- acquire-poll: this warp's 64 producers at step >= s ----
        for (;;) {
            int v0, v1;
            asm volatile("ld.acquire.gpu.global.b32 %0, [%1];" : "=r"(v0) : "l"(flag0) : "memory");
            asm volatile("ld.acquire.gpu.global.b32 %0, [%1];" : "=r"(v1) : "l"(flag1) : "memory");
            if (__all_sync(0xFFFFFFFFu, (v0 >= s) & (v1 >= s))) break;
            __nanosleep(64);
        }

        float acc[2][4][4];
#pragma unroll
        for (int a = 0; a < 2; a++)
#pragma unroll
            for (int b = 0; b < 4; b++)
#pragma unroll
                for (int c = 0; c < 4; c++) acc[a][b][c] = 0.f;

        const __half* hrow0 = hr + (size_t)(mh * 32 + f_r0) * NH + f_c * 8;
        const __half* hrow1 = hr + (size_t)(mh * 32 + f_r1) * NH + f_c * 8;

        // prologue: fill slots 0..R_PF-1 with t-blocks kh*32 + {0..11}
#pragma unroll
        for (int pb = 0; pb < R_PF; pb++) {
            int tb = kh * 32 + pb;
            cpa16(awbase + (unsigned)(pb * 1024 + f_r0 * 32 + f_c * 16), hrow0 + tb * 16);
            cpa16(awbase + (unsigned)(pb * 1024 + f_r1 * 32 + f_c * 16), hrow1 + tb * 16);
            cp_commit();
        }

        int slot = 0, fslot = R_PF;
        for (int t = 0; t < 32; t++) {
            if (t + R_PF < 32) {
                int tb = kh * 32 + t + R_PF;
                cpa16(awbase + (unsigned)(fslot * 1024 + f_r0 * 32 + f_c * 16), hrow0 + tb * 16);
                cpa16(awbase + (unsigned)(fslot * 1024 + f_r1 * 32 + f_c * 16), hrow1 + tb * 16);
                if (++fslot == R_SLOTS) fslot = 0;
            }
            cp_commit();          // empty group when nothing issued (keeps count aligned)
            cp_wait12();
            __syncwarp();

            const __half* Ab = Aw + slot * 512;
            const __half* Bt = Wsm + (kh * 32 + t) * 512;
            const int sl = (lc ^ (lr & 3)) * 4;

            unsigned bfr[4][2];
#pragma unroll
            for (int nt = 0; nt < 4; nt++) {
                uint2 v = *(const uint2*)(Bt + (nt * 8 + lr) * 16 + sl);
                bfr[nt][0] = v.x; bfr[nt][1] = v.y;
            }
            unsigned afr[4];
            {
                uint2 lo = *(const uint2*)(Ab + lr * 16 + sl);
                uint2 hi = *(const uint2*)(Ab + (lr + 8) * 16 + sl);
                afr[0] = lo.x; afr[1] = hi.x; afr[2] = lo.y; afr[3] = hi.y;
            }
            unsigned afr2[4];
            {
                uint2 lo = *(const uint2*)(Ab + (16 + lr) * 16 + sl);
                uint2 hi = *(const uint2*)(Ab + (24 + lr) * 16 + sl);
                afr2[0] = lo.x; afr2[1] = hi.x; afr2[2] = lo.y; afr2[3] = hi.y;
            }
#pragma unroll
            for (int nt = 0; nt < 4; nt++) {
                mma16(acc[0][nt], afr, bfr[nt]);
                mma16(acc[1][nt], afr2, bfr[nt]);
            }
            if (++slot == R_SLOTS) slot = 0;
        }

        // ---- disjoint partial stores: kh0 -> R0, kh1 -> R1 ----
        float* Rw = kh ? R1 : R0;
#pragma unroll
        for (int mt = 0; mt < 2; mt++)
#pragma unroll
            for (int nt = 0; nt < 4; nt++)
#pragma unroll
                for (int p = 0; p < 2; p++) {
                    int m = mh * 32 + mt * 16 + lr + p * 8;
                    *(float2*)(Rw + m * R_RSTRIDE + nt * 8 + 2 * lc) =
                        make_float2(acc[mt][nt][2 * p], acc[mt][nt][2 * p + 1]);
                }
        __syncthreads();

        // ---- epilogue: gates + cell + permuted/swizzled h store ----
#pragma unroll
        for (int q = 0; q < 2; q++) {
            int idx = tid + q * 256;
            int m = idx >> 2, u = idx & 3;
            const float* r0 = R0 + m * R_RSTRIDE + 2 * u;
            const float* r1 = R1 + m * R_RSTRIDE + 2 * u;
            float2 gi = *(const float2*)(r0 +  0); float2 gi1 = *(const float2*)(r1 +  0);
            float2 gf = *(const float2*)(r0 +  8); float2 gf1 = *(const float2*)(r1 +  8);
            float2 gg = *(const float2*)(r0 + 16); float2 gg1 = *(const float2*)(r1 + 16);
            float2 go = *(const float2*)(r0 + 24); float2 go1 = *(const float2*)(r1 + 24);
            float h0, h1;
            {
                float iv = sigf(gi.x + gi1.x + xgr[q][0].x);
                float fv = sigf(gf.x + gf1.x + xgr[q][1].x);
                float gv = tanhf_(gg.x + gg1.x + xgr[q][2].x);
                float ov = sigf(go.x + go1.x + xgr[q][3].x);
                creg[q][0] = fv * creg[q][0] + iv * gv;
                h0 = ov * tanhf_(creg[q][0]);
            }
            {
                float iv = sigf(gi.y + gi1.y + xgr[q][0].y);
                float fv = sigf(gf.y + gf1.y + xgr[q][1].y);
                float gv = tanhf_(gg.y + gg1.y + xgr[q][2].y);
                float ov = sigf(go.y + go1.y + xgr[q][3].y);
                creg[q][1] = fv * creg[q][1] + iv * gv;
                h1 = ov * tanhf_(creg[q][1]);
            }
            int slt = u ^ (m & 3);
            char* dst = (char*)hw + (size_t)m * 2048 + (cid >> 1) * 32 + slt * 8 + (cid & 1) * 4;
            *(__half2*)dst = __floats2half2_rn(h0, h1);
        }

        // publish: h stores -> fence -> barrier -> release flag
        __threadfence();
        __syncthreads();
        if (tid == 0)
            asm volatile("st.release.gpu.global.b32 [%0], %1;"
                         :: "l"(d_pflag + cid * 8), "r"(s + 1) : "memory");
    }
}

// ---------------- final FC: out = h_last @ W_fc.T + b_fc (un-permute) ----------------
__global__ void k_fc(const float* __restrict__ wfc, const float* __restrict__ bfc,
                     float* __restrict__ out) {
    int idx = blockIdx.x * 256 + threadIdx.x;
    if (idx >= NB * NO) return;
    int b = idx >> 6, o = idx & 63;
    const __half* hrow = &d_h16[0][0] + (size_t)b * NH;   // NS even -> final h in buffer 0
    const float* wrow = wfc + o * NH;
    float sacc = 0.f;
#pragma unroll 4
    for (int k = 0; k < NH; k++) {
        int j = (k >> 1) & 7;
        int p = j & 3, hs = j >> 2;
        int hi = (k >> 4) * 16 + (p ^ (b & 3)) * 4 + hs * 2 + (k & 1);
        sacc += __half2float(hrow[hi]) * __ldg(wrow + k);
    }
    out[idx] = sacc + bfc[o];
}

// ---------------- launch ----------------
extern "C" void kernel_launch(void* const* d_in, const int* in_sizes, int n_in,
                              void* d_out, int out_size) {
    const float* x    = (const float*)d_in[0];
    const float* mask = (const float*)d_in[1];
    const float* ti   = (const float*)d_in[2];
    const float* wih  = (const float*)d_in[3];
    const float* whh  = (const float*)d_in[4];
    const float* bih  = (const float*)d_in[5];
    const float* bhh  = (const float*)d_in[6];
    const float* wfc  = (const float*)d_in[7];
    const float* bfc  = (const float*)d_in[8];
    float* out = (float*)d_out;

    cudaFuncSetAttribute(k_xg, cudaFuncAttributeMaxDynamicSharedMemorySize, XG_SMEM);
    cudaFuncSetAttribute(k_rec, cudaFuncAttributeMaxDynamicSharedMemorySize, R_SMEM);

    k_prep_xt<<<(NS * NB * KP + 255) / 256, 256>>>(x, mask, ti);
    k_prep_w<<<(NG * NH + 255) / 256, 256>>>(wih, whh, bih, bhh);
    k_xg<<<dim3(64, 512), 256, XG_SMEM>>>();
    k_rec<<<128, 256, R_SMEM>>>();
    k_fc<<<(NB * NO + 255) / 256, 256>>>(wfc, bfc, out);
}